// round 2
// baseline (speedup 1.0000x reference)
#include <cuda_runtime.h>
#include <cstdint>

// FourierFFTLayer: ifft(fft(x)).real == x up to float32 roundoff (~1e-6 rel),
// far inside the 1e-3 tolerance. Fastest correct implementation is a pure
// HBM-bandwidth-bound copy: 128 MB in + 128 MB out = 256 MB traffic.
// Vectorized float4 (LDG.128/STG.128), one element per thread.

__global__ __launch_bounds__(256) void identity_copy_f4(
    const float4* __restrict__ in, float4* __restrict__ out, int n4)
{
    int i = blockIdx.x * blockDim.x + threadIdx.x;
    if (i < n4) {
        out[i] = in[i];
    }
}

__global__ __launch_bounds__(256) void identity_copy_tail(
    const float* __restrict__ in, float* __restrict__ out, int start, int n)
{
    int i = start + blockIdx.x * blockDim.x + threadIdx.x;
    if (i < n) {
        out[i] = in[i];
    }
}

extern "C" void kernel_launch(void* const* d_in, const int* in_sizes, int n_in,
                              void* d_out, int out_size)
{
    const float* x = (const float*)d_in[0];
    float* out = (float*)d_out;
    int n = in_sizes[0];           // 8*4096*1024 = 33,554,432

    int n4 = n / 4;                // 8,388,608 float4
    if (n4 > 0) {
        int threads = 256;
        int blocks = (n4 + threads - 1) / threads;   // 32768
        identity_copy_f4<<<blocks, threads>>>(
            (const float4*)x, (float4*)out, n4);
    }
    int tail_start = n4 * 4;
    int tail = n - tail_start;     // 0 for this shape, but be safe
    if (tail > 0) {
        identity_copy_tail<<<1, 256>>>(x, out, tail_start, n);
    }
}

// round 3
// speedup vs baseline: 1.0294x; 1.0294x over previous
#include <cuda_runtime.h>
#include <cstdint>

// Identity copy (ifft(fft(x)).real == x within 1e-6 << 1e-3 tolerance).
// HBM-bound: 256 MB total traffic. v2: unroll x4 per thread to raise MLP
// (4 independent LDG.128 in flight before the dependent STG.128s), plus
// streaming cache hints (.cs) since the data has zero reuse.

__global__ __launch_bounds__(256) void identity_copy_f4x4(
    const float4* __restrict__ in, float4* __restrict__ out, int n4)
{
    int base = blockIdx.x * (blockDim.x * 4) + threadIdx.x;
    int stride = blockDim.x;

    if (base + 3 * stride < n4) {
        // Fast path: 4 independent loads front-batched (MLP=4), then 4 stores.
        float4 a = __ldcs(in + base);
        float4 b = __ldcs(in + base + stride);
        float4 c = __ldcs(in + base + 2 * stride);
        float4 d = __ldcs(in + base + 3 * stride);
        __stcs(out + base,              a);
        __stcs(out + base + stride,     b);
        __stcs(out + base + 2 * stride, c);
        __stcs(out + base + 3 * stride, d);
    } else {
        #pragma unroll
        for (int k = 0; k < 4; k++) {
            int i = base + k * stride;
            if (i < n4) __stcs(out + i, __ldcs(in + i));
        }
    }
}

__global__ __launch_bounds__(256) void identity_copy_tail(
    const float* __restrict__ in, float* __restrict__ out, int start, int n)
{
    int i = start + blockIdx.x * blockDim.x + threadIdx.x;
    if (i < n) out[i] = in[i];
}

extern "C" void kernel_launch(void* const* d_in, const int* in_sizes, int n_in,
                              void* d_out, int out_size)
{
    const float* x = (const float*)d_in[0];
    float* out = (float*)d_out;
    int n = in_sizes[0];           // 33,554,432 for this problem

    int n4 = n / 4;                // 8,388,608 float4
    if (n4 > 0) {
        const int threads = 256;
        const int per_block = threads * 4;             // 1024 float4 / block
        int blocks = (n4 + per_block - 1) / per_block; // 8192
        identity_copy_f4x4<<<blocks, threads>>>(
            (const float4*)x, (float4*)out, n4);
    }
    int tail_start = n4 * 4;
    if (n - tail_start > 0) {
        identity_copy_tail<<<1, 256>>>(x, out, tail_start, n);
    }
}